// round 17
// baseline (speedup 1.0000x reference)
#include <cuda_runtime.h>

typedef unsigned long long u64;

#define B_   32
#define ICN  8
#define OCN  8
#define HH   512
#define WW   512
#define MC_  32

// Scratch: per-sample packed filters {w,w} [b][oc][ic][9] and bias [b][oc]
__device__ u64   g_filtp[B_ * OCN * ICN * 9];
__device__ float g_bias [B_ * OCN];

// ---------------- f32x2 helpers (Blackwell packed fp32) ----------------
__device__ __forceinline__ u64 pack2(float lo, float hi) {
    u64 r;
    asm("mov.b64 %0, {%1, %2};" : "=l"(r) : "f"(lo), "f"(hi));
    return r;
}
__device__ __forceinline__ void ffma2(u64 &d, u64 a, u64 b) {
    asm("fma.rn.f32x2 %0, %1, %2, %0;" : "+l"(d) : "l"(a), "l"(b));
}
__device__ __forceinline__ float2 unpack2(u64 v) {
    float2 f;
    asm("mov.b64 {%0, %1}, %2;" : "=f"(f.x), "=f"(f.y) : "l"(v));
    return f;
}

// ---------------- Kernel A: hypernetwork (tiny) ----------------
__global__ void setup_kernel(const float* __restrict__ q,  const float* __restrict__ wm1,
                             const float* __restrict__ bm1, const float* __restrict__ wm2,
                             const float* __restrict__ bm2, const float* __restrict__ wt,
                             const float* __restrict__ bt,  const float* __restrict__ wb,
                             const float* __restrict__ bb) {
    const int b   = blockIdx.x;
    const int tid = threadIdx.x;   // 128 threads

    __shared__ float m1[MC_];
    __shared__ float m2[MC_];

    if (tid < MC_) {
        const float* qb = q + b * 64;
        const float* w  = wm1 + tid * 64;
        float s = bm1[tid];
        #pragma unroll
        for (int j = 0; j < 64; j++) s += qb[j] * w[j];
        m1[tid] = s > 0.f ? s : 0.01f * s;
    }
    __syncthreads();

    if (tid < MC_) {
        const float* w = wm2 + tid * MC_;
        float s = bm2[tid];
        #pragma unroll
        for (int k = 0; k < MC_; k++) s += m1[k] * w[k];
        m2[tid] = s > 0.f ? s : 0.01f * s;
    }
    __syncthreads();

    for (int idx = tid; idx < OCN * ICN * 9; idx += 128) {
        float s = bt[idx / 9];
        #pragma unroll
        for (int c = 0; c < MC_; c++) s += m2[c] * wt[c * (OCN * ICN * 9) + idx];
        g_filtp[b * (OCN * ICN * 9) + idx] = pack2(s, s);
    }

    if (tid < OCN) {
        float s = bb[tid];
        #pragma unroll
        for (int c = 0; c < MC_; c++) s += m2[c] * wb[tid * MC_ + c];
        g_bias[b * OCN + tid] = s;
    }
}

// ---------------- Kernel B: per-sample 3x3 conv, smem-staged ----------------
// Block = 256 threads = 64 col-threads x 4 rowPairs. Covers 8 output rows x
// 512 cols for 4 output channels of one sample. Per ic, the 10 needed input
// rows are staged into SMEM once (no halo duplication, bulk independent LDGs),
// then all row reads are 29-cycle LDS.

// Read 10 values (cols c0-1 .. c0+8) of a staged row from SMEM.
__device__ __forceinline__ void read_row(const float* __restrict__ srow, int c0,
                                         int colIdx, float r[10]) {
    float4 m0 = *(const float4*)(srow + c0);
    float4 m1 = *(const float4*)(srow + c0 + 4);
    r[0] = (colIdx > 0)  ? srow[c0 - 1] : 0.f;   // block-left edge == image edge
    r[1] = m0.x; r[2] = m0.y; r[3] = m0.z; r[4] = m0.w;
    r[5] = m1.x; r[6] = m1.y; r[7] = m1.z; r[8] = m1.w;
    r[9] = (colIdx < 63) ? srow[c0 + 8] : 0.f;
}

// One dy tap: pack rows (ra -> lo lane = row h0, rb -> hi lane = row h0+1),
// feed 4 ocs x 8 cols x 3 dx. Weights are pre-packed u64 broadcast LDS.64.
__device__ __forceinline__ void conv_dy(const u64 (*__restrict__ sfw)[ICN][9], int ic, int dy,
                                        const float ra[10], const float rb[10],
                                        u64 acc[4][8]) {
    u64 p[10];
    #pragma unroll
    for (int j = 0; j < 10; j++) p[j] = pack2(ra[j], rb[j]);

    #pragma unroll
    for (int oc = 0; oc < 4; oc++) {
        const u64 W0 = sfw[oc][ic][dy * 3 + 0];
        const u64 W1 = sfw[oc][ic][dy * 3 + 1];
        const u64 W2 = sfw[oc][ic][dy * 3 + 2];
        #pragma unroll
        for (int j = 0; j < 8; j++) {
            ffma2(acc[oc][j], p[j],     W0);
            ffma2(acc[oc][j], p[j + 1], W1);
            ffma2(acc[oc][j], p[j + 2], W2);
        }
    }
}

__global__ void __launch_bounds__(256, 2)
conv_kernel(const float* __restrict__ x, float* __restrict__ y) {
    const int tid     = threadIdx.x;
    const int colIdx  = tid & 63;       // 64 column-threads, 8 cols each
    const int rowPair = tid >> 6;       // 4 row-pairs -> 8 rows per block
    const int b       = blockIdx.z;
    const int oc0     = blockIdx.y * 4; // oc quad
    const int hbase   = blockIdx.x * 8; // block's first output row
    const int h0      = hbase + rowPair * 2;
    const int c0      = colIdx * 8;

    __shared__ float stile[10][WW];     // rows hbase-1 .. hbase+8  (20 KB)
    __shared__ u64   sfw[4][ICN][9];    // pre-packed {w,w} weights
    __shared__ float sbias[4];

    for (int i = tid; i < 4 * ICN * 9; i += 256) {
        int ocl = i / (ICN * 9);
        int rem = i - ocl * (ICN * 9);
        sfw[ocl][rem / 9][rem % 9] =
            g_filtp[b * (OCN * ICN * 9) + (oc0 + ocl) * (ICN * 9) + rem];
    }
    if (tid < 4) sbias[tid] = g_bias[b * OCN + oc0 + tid];

    u64 acc[4][8];
    #pragma unroll
    for (int oc = 0; oc < 4; oc++) {
        // sbias written by this thread group before any sync: read via global instead
        u64 bz = pack2(g_bias[b * OCN + oc0 + oc], g_bias[b * OCN + oc0 + oc]);
        #pragma unroll
        for (int j = 0; j < 8; j++) acc[oc][j] = bz;
    }

    const float* xb = x + (size_t)b * ICN * HH * WW;
    const int lr0 = rowPair * 2;        // local index of row h0-1 in stile

    #pragma unroll 1
    for (int ic = 0; ic < ICN; ic++) {
        const float* xc = xb + (size_t)ic * HH * WW;

        __syncthreads();                // previous ic's readers done
        // Cooperative stage: 10 rows x 512 cols = 1280 float4, 5 per thread.
        #pragma unroll
        for (int k = 0; k < 5; k++) {
            int idx = tid + 256 * k;    // float4 index 0..1279
            int lr  = idx >> 7;         // local row 0..9
            int c4  = (idx & 127) << 2; // col 0..508
            int h   = hbase - 1 + lr;
            float4 v = (h >= 0 && h < HH) ? *(const float4*)(xc + (size_t)h * WW + c4)
                                          : make_float4(0.f, 0.f, 0.f, 0.f);
            *(float4*)&stile[lr][c4] = v;
        }
        __syncthreads();

        float ra[10], rb[10];
        read_row(stile[lr0],     c0, colIdx, ra);
        read_row(stile[lr0 + 1], c0, colIdx, rb);
        conv_dy(sfw, ic, 0, ra, rb, acc);          // rows (h0-1, h0)
        read_row(stile[lr0 + 2], c0, colIdx, ra);
        conv_dy(sfw, ic, 1, rb, ra, acc);          // rows (h0,   h0+1)
        read_row(stile[lr0 + 3], c0, colIdx, rb);
        conv_dy(sfw, ic, 2, ra, rb, acc);          // rows (h0+1, h0+2)
    }

    // Epilogue: unpack f32x2 lanes (lo = row h0, hi = row h0+1), float4 stores.
    #pragma unroll
    for (int oc = 0; oc < 4; oc++) {
        float lo[8], hi[8];
        #pragma unroll
        for (int j = 0; j < 8; j++) { float2 f = unpack2(acc[oc][j]); lo[j] = f.x; hi[j] = f.y; }
        float* p0 = y + (((size_t)(b * OCN + oc0 + oc)) * HH + h0) * WW + c0;
        *(float4*)(p0)          = make_float4(lo[0], lo[1], lo[2], lo[3]);
        *(float4*)(p0 + 4)      = make_float4(lo[4], lo[5], lo[6], lo[7]);
        *(float4*)(p0 + WW)     = make_float4(hi[0], hi[1], hi[2], hi[3]);
        *(float4*)(p0 + WW + 4) = make_float4(hi[4], hi[5], hi[6], hi[7]);
    }
}

// ---------------- launch ----------------
extern "C" void kernel_launch(void* const* d_in, const int* in_sizes, int n_in,
                              void* d_out, int out_size) {
    const float* q   = (const float*)d_in[0];
    const float* x   = (const float*)d_in[1];
    const float* wm1 = (const float*)d_in[2];
    const float* bm1 = (const float*)d_in[3];
    const float* wm2 = (const float*)d_in[4];
    const float* bm2 = (const float*)d_in[5];
    const float* wt  = (const float*)d_in[6];
    const float* bt  = (const float*)d_in[7];
    const float* wb  = (const float*)d_in[8];
    const float* bb  = (const float*)d_in[9];
    float* y = (float*)d_out;

    setup_kernel<<<B_, 128>>>(q, wm1, bm1, wm2, bm2, wt, bt, wb, bb);

    dim3 grid(HH / 8, OCN / 4, B_);   // 64 x 2 x 32 = 4096 CTAs
    conv_kernel<<<grid, 256>>>(x, y);
}